// round 12
// baseline (speedup 1.0000x reference)
#include <cuda_runtime.h>

// out = noised + 0.1f * noise   (elementwise, fp32)
// N = 64*3*512*512 = 50,331,648 (divisible by 4). Traffic floor 604 MB/pass.
//
// Measured landscape (bench dur_us is the scoring metric):
//   float4 plain (R4):        kernel 82.3, bench 88.9  <- best bench
//   float4 .cs VPT4 (R5):     kernel 83.1, bench 90.2
//   v8 .nc+.cs (R6):          kernel 80.1, bench 90.5
//   v8 .nc hints (R8):        kernel 79.4, bench 90.4  <- best kernel
//   v8 plain (R9):            kernel 81.2, bench 90.2
// Wider/exotic access paths win in ncu's isolated cold-cache capture but lose
// more in the sustained graph-replay loop the bench actually times. R10:
// lock in the float4/plain/256-thread config (exact R4 reproduction).

__global__ void __launch_bounds__(256)
gaussian_noise_add_kernel(const float4* __restrict__ noised,
                          const float4* __restrict__ noise,
                          float4* __restrict__ out,
                          int n4)
{
    int i = blockIdx.x * blockDim.x + threadIdx.x;
    if (i < n4) {
        float4 a = noised[i];
        float4 b = noise[i];
        float4 r;
        r.x = fmaf(0.1f, b.x, a.x);
        r.y = fmaf(0.1f, b.y, a.y);
        r.z = fmaf(0.1f, b.z, a.z);
        r.w = fmaf(0.1f, b.w, a.w);
        out[i] = r;
    }
}

// Scalar tail kernel (defensive; n is divisible by 4 for this problem so it
// is not launched).
__global__ void gaussian_noise_tail_kernel(const float* __restrict__ noised,
                                           const float* __restrict__ noise,
                                           float* __restrict__ out,
                                           int start, int n)
{
    int i = start + blockIdx.x * blockDim.x + threadIdx.x;
    if (i < n) {
        out[i] = fmaf(0.1f, noise[i], noised[i]);
    }
}

extern "C" void kernel_launch(void* const* d_in, const int* in_sizes, int n_in,
                              void* d_out, int out_size)
{
    const float* noised = (const float*)d_in[0];
    const float* noise  = (const float*)d_in[1];
    float* out = (float*)d_out;
    int n = in_sizes[0];

    int n4 = n >> 2;
    if (n4 > 0) {
        int threads = 256;
        int blocks = (n4 + threads - 1) / threads;
        gaussian_noise_add_kernel<<<blocks, threads>>>(
            (const float4*)noised, (const float4*)noise, (float4*)out, n4);
    }
    int rem = n - (n4 << 2);
    if (rem > 0) {
        gaussian_noise_tail_kernel<<<1, 256>>>(noised, noise, out, n4 << 2, n);
    }
}

// round 13
// speedup vs baseline: 1.0040x; 1.0040x over previous
#include <cuda_runtime.h>

// out = noised + 0.1f * noise   (elementwise, fp32)
// N = 64*3*512*512 = 50,331,648 (divisible by 4). Traffic floor 604 MB/pass.
//
// Measured landscape (bench dur_us is the scoring metric):
//   float4 plain, 256thr (R4/R10):  kernel 82.3/81.5, bench 88.9/88.8  <- best, reproduced
//   float4 .cs VPT4 (R5):           bench 90.2
//   v8 .nc+.cs (R6):                bench 90.5   (kernel 79-80us but replay gap +4us)
//   v8 plain (R9):                  bench 90.2
//   persistent grid-stride (R7):    bench 97.2
// Conclusion: simple float4 generic-path is bench-optimal. R11 probes the one
// untested residual: block=512 (same access pattern, half the CTAs).

__global__ void __launch_bounds__(512)
gaussian_noise_add_kernel(const float4* __restrict__ noised,
                          const float4* __restrict__ noise,
                          float4* __restrict__ out,
                          int n4)
{
    int i = blockIdx.x * blockDim.x + threadIdx.x;
    if (i < n4) {
        float4 a = noised[i];
        float4 b = noise[i];
        float4 r;
        r.x = fmaf(0.1f, b.x, a.x);
        r.y = fmaf(0.1f, b.y, a.y);
        r.z = fmaf(0.1f, b.z, a.z);
        r.w = fmaf(0.1f, b.w, a.w);
        out[i] = r;
    }
}

// Scalar tail kernel (defensive; n is divisible by 4 for this problem so it
// is not launched).
__global__ void gaussian_noise_tail_kernel(const float* __restrict__ noised,
                                           const float* __restrict__ noise,
                                           float* __restrict__ out,
                                           int start, int n)
{
    int i = start + blockIdx.x * blockDim.x + threadIdx.x;
    if (i < n) {
        out[i] = fmaf(0.1f, noise[i], noised[i]);
    }
}

extern "C" void kernel_launch(void* const* d_in, const int* in_sizes, int n_in,
                              void* d_out, int out_size)
{
    const float* noised = (const float*)d_in[0];
    const float* noise  = (const float*)d_in[1];
    float* out = (float*)d_out;
    int n = in_sizes[0];

    int n4 = n >> 2;
    if (n4 > 0) {
        int threads = 512;
        int blocks = (n4 + threads - 1) / threads;
        gaussian_noise_add_kernel<<<blocks, threads>>>(
            (const float4*)noised, (const float4*)noise, (float4*)out, n4);
    }
    int rem = n - (n4 << 2);
    if (rem > 0) {
        gaussian_noise_tail_kernel<<<1, 256>>>(noised, noise, out, n4 << 2, n);
    }
}